// round 6
// baseline (speedup 1.0000x reference)
#include <cuda_runtime.h>
#include <math.h>

#define BB   4
#define HWSZ 16384        // 128*128

// ---------------- scratch (device globals: no allocation allowed) ----------------
__device__ float g_highup[16777216];  // (4,256,128,128)
__device__ float g_query [ 8388608];  // (4,128,128,128)
__device__ float g_value [ 8388608];
__device__ float g_pv    [ 8388608];
__device__ float g_tmp   [ 8388608];
__device__ float g_pq    [ 1048576];  // (4,16,128,128)
__device__ float g_pk    [ 1048576];
__device__ float g_att   [16777216];  // (4,128,128,256) exp(logits)
__device__ float g_tot   [   65536];  // (4,128,128) softmax denominators

// ---------------- tf32 helpers ----------------
__device__ __forceinline__ unsigned f2tf(float f) {
    unsigned r;
    asm("cvt.rna.tf32.f32 %0, %1;" : "=r"(r) : "f"(f));
    return r;
}

__device__ __forceinline__ void mma8(float* d, const unsigned* a, const unsigned* b) {
    asm("mma.sync.aligned.m16n8k8.row.col.f32.tf32.tf32.f32 "
        "{%0,%1,%2,%3},{%4,%5,%6,%7},{%8,%9},{%0,%1,%2,%3};"
        : "+f"(d[0]), "+f"(d[1]), "+f"(d[2]), "+f"(d[3])
        : "r"(a[0]), "r"(a[1]), "r"(a[2]), "r"(a[3]), "r"(b[0]), "r"(b[1]));
}

// One K=16 chunk from staged smem tiles. Warp tile 64x32 (4 m x 4 n of 16x8 mmas).
__device__ __forceinline__ void tile_mma(const unsigned (*As)[136],
                                         const unsigned (*Bs)[136],
                                         float acc[4][4][4],
                                         int lane, int mbase, int nbase)
{
#pragma unroll
    for (int kt = 0; kt < 2; kt++) {
        unsigned a[4][4], b[4][2];
        const int kb = kt * 8 + (lane & 3);
        const int rq = lane >> 2;
#pragma unroll
        for (int mt = 0; mt < 4; mt++) {
            int m = mbase + mt * 16 + rq;
            a[mt][0] = As[kb][m];
            a[mt][1] = As[kb][m + 8];
            a[mt][2] = As[kb + 4][m];
            a[mt][3] = As[kb + 4][m + 8];
        }
#pragma unroll
        for (int nt = 0; nt < 4; nt++) {
            int n = nbase + nt * 8 + rq;
            b[nt][0] = Bs[kb][n];
            b[nt][1] = Bs[kb + 4][n];
        }
#pragma unroll
        for (int mt = 0; mt < 4; mt++)
#pragma unroll
            for (int nt = 0; nt < 4; nt++)
                mma8(acc[mt][nt], a[mt], b[nt]);
    }
}

// ---------------- bilinear 2x upsample ----------------
__global__ __launch_bounds__(256) void upsample_kernel(const float* __restrict__ in,
                                                       float* __restrict__ out) {
    int idx = blockIdx.x * 256 + threadIdx.x;
    int ox = idx & 127;
    int oy = (idx >> 7) & 127;
    int bc = idx >> 14;
    float fy = 0.5f * oy - 0.25f;
    float fx = 0.5f * ox - 0.25f;
    int y0 = (int)floorf(fy); float wy = fy - (float)y0;
    int x0 = (int)floorf(fx); float wx = fx - (float)x0;
    int y1 = min(y0 + 1, 63); y0 = max(y0, 0);
    int x1 = min(x0 + 1, 63); x0 = max(x0, 0);
    const float* p = in + (size_t)bc * 4096;
    float v00 = p[y0 * 64 + x0], v01 = p[y0 * 64 + x1];
    float v10 = p[y1 * 64 + x0], v11 = p[y1 * 64 + x1];
    float top = v00 + wx * (v01 - v00);
    float bot = v10 + wx * (v11 - v10);
    out[idx] = top + wy * (bot - top);
}

// ---------------- dual-input tf32 GEMM (double-buffered smem) ----------------
__global__ __launch_bounds__(256) void gemm_dual(
    const float* __restrict__ Wm, int ldw,
    const float* __restrict__ bias,
    const float* __restrict__ X1, int I1,
    const float* __restrict__ X2, int I2,
    float* __restrict__ Y, int O,
    const float* __restrict__ bng, const float* __restrict__ bnb,
    const float* __restrict__ bnm, const float* __restrict__ bnv)
{
    __shared__ unsigned As[2][16][136];
    __shared__ unsigned Bs[2][16][136];
    const int b  = blockIdx.z;
    const int to = blockIdx.y * 128;
    const int tp = blockIdx.x * 128;
    const int tid  = threadIdx.x;
    const int warp = tid >> 5;
    const int lane = tid & 31;
    const int mbase = (warp >> 2) * 64;
    const int nbase = (warp & 3) * 32;

    const int am  = tid >> 1;
    const int akq = (tid & 1) * 8;
    const int bk  = tid >> 4;
    const int bn  = (tid & 15) * 8;

    const float* X1p = X1 + (size_t)b * I1 * HWSZ;
    const float* X2p = X2 ? X2 + (size_t)b * I2 * HWSZ : nullptr;
    const int K  = I1 + I2;
    const int nK = K >> 4;

    float acc[4][4][4] = {};
    float4 w0, w1, x0, x1;

    auto loadG = [&](int k0) {
        const float* Wp = Wm + (size_t)(to + am) * ldw + k0 + akq;
        w0 = *(const float4*)Wp;
        w1 = *(const float4*)(Wp + 4);
        int kr = k0 + bk;
        const float* Xp = (kr < I1) ? (X1p + (size_t)kr * HWSZ)
                                    : (X2p + (size_t)(kr - I1) * HWSZ);
        Xp += tp + bn;
        x0 = *(const float4*)Xp;
        x1 = *(const float4*)(Xp + 4);
    };
    auto storeS = [&](int buf) {
        As[buf][akq + 0][am] = f2tf(w0.x);
        As[buf][akq + 1][am] = f2tf(w0.y);
        As[buf][akq + 2][am] = f2tf(w0.z);
        As[buf][akq + 3][am] = f2tf(w0.w);
        As[buf][akq + 4][am] = f2tf(w1.x);
        As[buf][akq + 5][am] = f2tf(w1.y);
        As[buf][akq + 6][am] = f2tf(w1.z);
        As[buf][akq + 7][am] = f2tf(w1.w);
        *(uint4*)&Bs[buf][bk][bn]     = make_uint4(f2tf(x0.x), f2tf(x0.y), f2tf(x0.z), f2tf(x0.w));
        *(uint4*)&Bs[buf][bk][bn + 4] = make_uint4(f2tf(x1.x), f2tf(x1.y), f2tf(x1.z), f2tf(x1.w));
    };

    loadG(0);
    storeS(0);
    __syncthreads();
    for (int kt = 0; kt < nK; kt++) {
        if (kt + 1 < nK) loadG((kt + 1) << 4);
        tile_mma(As[kt & 1], Bs[kt & 1], acc, lane, mbase, nbase);
        if (kt + 1 < nK) storeS((kt + 1) & 1);
        __syncthreads();
    }

    const bool dobn = (bng != nullptr);
#pragma unroll
    for (int mt = 0; mt < 4; mt++) {
#pragma unroll
        for (int half = 0; half < 2; half++) {
            int o = to + mbase + mt * 16 + (lane >> 2) + half * 8;
            float bia = bias ? bias[o] : 0.0f;
            float sc = 1.0f, mn = 0.0f, bt = 0.0f;
            if (dobn) {
                sc = bng[o] * rsqrtf(bnv[o] + 1e-5f);
                mn = bnm[o];
                bt = bnb[o];
            }
            size_t rowb = ((size_t)b * O + o) * HWSZ + tp;
#pragma unroll
            for (int nt = 0; nt < 4; nt++) {
                int n = nbase + nt * 8 + 2 * (lane & 3);
                float v0 = acc[mt][nt][half * 2 + 0] + bia;
                float v1 = acc[mt][nt][half * 2 + 1] + bia;
                if (dobn) {
                    v0 = fmaxf((v0 - mn) * sc + bt, 0.0f);
                    v1 = fmaxf((v1 - mn) * sc + bt, 0.0f);
                }
                *(float2*)(Y + rowb + n) = make_float2(v0, v1);
            }
        }
    }
}

// ---------------- small projection O=16, I=128 with 4-pixel ILP ----------------
__global__ __launch_bounds__(256) void proj16_kernel(
    const float* __restrict__ Wm, const float* __restrict__ bias,
    const float* __restrict__ X, float* __restrict__ Y)
{
    __shared__ float Ws[16 * 128];
    const int b = blockIdx.y;
    const int p = blockIdx.x * 1024 + threadIdx.x * 4;
    for (int i = threadIdx.x; i < 2048; i += 256) Ws[i] = Wm[i];
    __syncthreads();
    float4 acc[16];
#pragma unroll
    for (int o = 0; o < 16; o++) {
        float bb = bias[o];
        acc[o] = make_float4(bb, bb, bb, bb);
    }
    const float* Xp = X + (size_t)b * 128 * HWSZ + p;
#pragma unroll 4
    for (int i = 0; i < 128; i++) {
        float4 xv = *(const float4*)(Xp + (size_t)i * HWSZ);
#pragma unroll
        for (int o = 0; o < 16; o++) {
            float wv = Ws[o * 128 + i];
            acc[o].x += wv * xv.x;
            acc[o].y += wv * xv.y;
            acc[o].z += wv * xv.z;
            acc[o].w += wv * xv.w;
        }
    }
    float* Yp = Y + (size_t)b * 16 * HWSZ + p;
#pragma unroll
    for (int o = 0; o < 16; o++) *(float4*)(Yp + (size_t)o * HWSZ) = acc[o];
}

// ---------------- criss-cross logits -> exp + row-sum (softmax fused out) ----------------
// eH: att[b,h,w,x] = exp(sum_c pq[c,h,w]*pk[c,x,w]), 0 on diag; tot[b,h,w] = sum_x (plain store)
__global__ __launch_bounds__(256) void eH_kernel(const float* __restrict__ pq,
                                                 const float* __restrict__ pk,
                                                 float* __restrict__ att,
                                                 float* __restrict__ tot)
{
    __shared__ float PQ[16][128];
    __shared__ float PK[16][128];
    __shared__ float ws[64][8];
    const int w = blockIdx.x, b = blockIdx.y;
    for (int i = threadIdx.x; i < 2048; i += 256) {
        int c = i >> 7, h = i & 127;
        size_t idx = (((size_t)b * 16 + c) * 128 + h) * 128 + w;
        PQ[c][h] = pq[idx];
        PK[c][h] = pk[idx];
    }
    __syncthreads();
    const int x    = threadIdx.x & 127;
    const int h0   = threadIdx.x >> 7;
    const int warp = threadIdx.x >> 5;
    const int lane = threadIdx.x & 31;
    for (int j = 0; j < 64; j++) {
        int h = 2 * j + h0;
        float s = 0.0f;
#pragma unroll
        for (int c = 0; c < 16; c++) s += PQ[c][h] * PK[c][x];
        float e = (h == x) ? 0.0f : __expf(s);
        att[(((size_t)b * 128 + h) * 128 + w) * 256 + x] = e;
        float p = e;
#pragma unroll
        for (int o = 16; o; o >>= 1) p += __shfl_xor_sync(0xffffffffu, p, o);
        if (lane == 0) ws[j][warp] = p;
    }
    __syncthreads();
    if (threadIdx.x < 128) {
        int h = threadIdx.x;
        int j = h >> 1, g = (h & 1) * 4;
        float s = ws[j][g] + ws[j][g + 1] + ws[j][g + 2] + ws[j][g + 3];
        tot[((size_t)b * 128 + h) * 128 + w] = s;
    }
}

// eW: att[b,h,w,128+x] = exp(sum_c pq[c,h,w]*pk[c,h,x]); tot[b,h,w] += sum_x
__global__ __launch_bounds__(256) void eW_kernel(const float* __restrict__ pq,
                                                 const float* __restrict__ pk,
                                                 float* __restrict__ att,
                                                 float* __restrict__ tot)
{
    __shared__ float PQ[16][128];
    __shared__ float PK[16][128];
    __shared__ float ws[64][8];
    const int h = blockIdx.x, b = blockIdx.y;
    for (int i = threadIdx.x; i < 2048; i += 256) {
        int c = i >> 7, w = i & 127;
        size_t idx = (((size_t)b * 16 + c) * 128 + h) * 128 + w;
        PQ[c][w] = pq[idx];
        PK[c][w] = pk[idx];
    }
    __syncthreads();
    const int x    = threadIdx.x & 127;
    const int w0   = threadIdx.x >> 7;
    const int warp = threadIdx.x >> 5;
    const int lane = threadIdx.x & 31;
    for (int j = 0; j < 64; j++) {
        int w = 2 * j + w0;
        float s = 0.0f;
#pragma unroll
        for (int c = 0; c < 16; c++) s += PQ[c][w] * PK[c][x];
        float e = __expf(s);
        att[(((size_t)b * 128 + h) * 128 + w) * 256 + 128 + x] = e;
        float p = e;
#pragma unroll
        for (int o = 16; o; o >>= 1) p += __shfl_xor_sync(0xffffffffu, p, o);
        if (lane == 0) ws[j][warp] = p;
    }
    __syncthreads();
    if (threadIdx.x < 128) {
        int w = threadIdx.x;
        int j = w >> 1, g = (w & 1) * 4;
        float s = ws[j][g] + ws[j][g + 1] + ws[j][g + 2] + ws[j][g + 3];
        size_t idx = ((size_t)b * 128 + h) * 128 + w;
        tot[idx] += s;        // eH already stored; kernels serialize on stream
    }
}

// ---------------- aggH: tmp[b,c,h,w] = inv[h,w] * sum_x pv[b,c,x,w]*attH (double-buffered) ----
__global__ __launch_bounds__(256) void aggH_mma(const float* __restrict__ pv,
                                                const float* __restrict__ att,
                                                const float* __restrict__ tot,
                                                float* __restrict__ tmp)
{
    __shared__ unsigned As[2][16][136];
    __shared__ unsigned Bs[2][16][136];
    __shared__ float invs[128];
    const int w = blockIdx.x, b = blockIdx.y;
    const int tid  = threadIdx.x;
    const int warp = tid >> 5;
    const int lane = tid & 31;
    const int mbase = (warp >> 2) * 64;
    const int nbase = (warp & 3) * 32;

    const int cm = tid >> 1;
    const int xq = (tid & 1) * 8;

    if (tid < 128)
        invs[tid] = 1.0f / tot[((size_t)b * 128 + tid) * 128 + w];

    float acc[4][4][4] = {};
    const float* pvp = pv + (((size_t)b * 128 + cm) * 128) * 128 + w;
    const float* atp = att + (((size_t)b * 128 + cm) * 128 + w) * 256;

    float av[8];
    float4 b0, b1;
    auto loadG = [&](int k0) {
#pragma unroll
        for (int j = 0; j < 8; j++) av[j] = pvp[(size_t)(k0 + xq + j) * 128];
        b0 = *(const float4*)(atp + k0 + xq);
        b1 = *(const float4*)(atp + k0 + xq + 4);
    };
    auto storeS = [&](int buf) {
#pragma unroll
        for (int j = 0; j < 8; j++) As[buf][xq + j][cm] = f2tf(av[j]);
        Bs[buf][xq + 0][cm] = f2tf(b0.x);
        Bs[buf][xq + 1][cm] = f2tf(b0.y);
        Bs[buf][xq + 2][cm] = f2tf(b0.z);
        Bs[buf][xq + 3][cm] = f2tf(b0.w);
        Bs[buf][xq + 4][cm] = f2tf(b1.x);
        Bs[buf][xq + 5][cm] = f2tf(b1.y);
        Bs[buf][xq + 6][cm] = f2tf(b1.z);
        Bs[buf][xq + 7][cm] = f2tf(b1.w);
    };

    loadG(0);
    storeS(0);
    __syncthreads();
    for (int kt = 0; kt < 8; kt++) {
        if (kt < 7) loadG((kt + 1) << 4);
        tile_mma(As[kt & 1], Bs[kt & 1], acc, lane, mbase, nbase);
        if (kt < 7) storeS((kt + 1) & 1);
        __syncthreads();
    }

#pragma unroll
    for (int mt = 0; mt < 4; mt++)
#pragma unroll
        for (int half = 0; half < 2; half++) {
            int c = mbase + mt * 16 + (lane >> 2) + half * 8;
            size_t cb = (((size_t)b * 128 + c) * 128) * 128 + w;
#pragma unroll
            for (int nt = 0; nt < 4; nt++) {
                int h = nbase + nt * 8 + 2 * (lane & 3);
                tmp[cb + (size_t)h * 128]       = acc[mt][nt][half * 2 + 0] * invs[h];
                tmp[cb + (size_t)(h + 1) * 128] = acc[mt][nt][half * 2 + 1] * invs[h + 1];
            }
        }
}

// ---------------- aggW + update: value += gamma*(tmp + inv[h,w]*sum_x pv*attW) -----------
__global__ __launch_bounds__(256) void aggW_mma(const float* __restrict__ pv,
                                                const float* __restrict__ att,
                                                const float* __restrict__ tot,
                                                const float* __restrict__ tmp,
                                                float* __restrict__ value,
                                                const float* __restrict__ gamma_p)
{
    __shared__ unsigned As[2][16][136];
    __shared__ unsigned Bs[2][16][136];
    __shared__ float invs[128];
    const int h = blockIdx.x, b = blockIdx.y;
    const int tid  = threadIdx.x;
    const int warp = tid >> 5;
    const int lane = tid & 31;
    const int mbase = (warp >> 2) * 64;
    const int nbase = (warp & 3) * 32;

    const int cm = tid >> 1;
    const int xq = (tid & 1) * 8;

    if (tid < 128)
        invs[tid] = 1.0f / tot[((size_t)b * 128 + h) * 128 + tid];

    float acc[4][4][4] = {};
    const float* pvp = pv + (((size_t)b * 128 + cm) * 128 + h) * 128;
    const float* atp = att + (((size_t)b * 128 + h) * 128 + cm) * 256 + 128;

    float4 a0, a1, b0, b1;
    auto loadG = [&](int k0) {
        a0 = *(const float4*)(pvp + k0 + xq);
        a1 = *(const float4*)(pvp + k0 + xq + 4);
        b0 = *(const float4*)(atp + k0 + xq);
        b1 = *(const float4*)(atp + k0 + xq + 4);
    };
    auto storeS = [&](int buf) {
        As[buf][xq + 0][cm] = f2tf(a0.x);
        As[buf][xq + 1][cm] = f2tf(a0.y);
        As[buf][xq + 2][cm] = f2tf(a0.z);
        As[buf][xq + 3][cm] = f2tf(a0.w);
        As[buf][xq + 4][cm] = f2tf(a1.x);
        As[buf][xq + 5][cm] = f2tf(a1.y);
        As[buf][xq + 6][cm] = f2tf(a1.z);
        As[buf][xq + 7][cm] = f2tf(a1.w);
        Bs[buf][xq + 0][cm] = f2tf(b0.x);
        Bs[buf][xq + 1][cm] = f2tf(b0.y);
        Bs[buf][xq + 2][cm] = f2tf(b0.z);
        Bs[buf][xq + 3][cm] = f2tf(b0.w);
        Bs[buf][xq + 4][cm] = f2tf(b1.x);
        Bs[buf][xq + 5][cm] = f2tf(b1.y);
        Bs[buf][xq + 6][cm] = f2tf(b1.z);
        Bs[buf][xq + 7][cm] = f2tf(b1.w);
    };

    loadG(0);
    storeS(0);
    __syncthreads();
    for (int kt = 0; kt < 8; kt++) {
        if (kt < 7) loadG((kt + 1) << 4);
        tile_mma(As[kt & 1], Bs[kt & 1], acc, lane, mbase, nbase);
        if (kt < 7) storeS((kt + 1) & 1);
        __syncthreads();
    }

    const float g = *gamma_p;
#pragma unroll
    for (int mt = 0; mt < 4; mt++)
#pragma unroll
        for (int half = 0; half < 2; half++) {
            int c = mbase + mt * 16 + (lane >> 2) + half * 8;
            size_t rowb = (((size_t)b * 128 + c) * 128 + h) * 128;
#pragma unroll
            for (int nt = 0; nt < 4; nt++) {
                int n = nbase + nt * 8 + 2 * (lane & 3);
                float2 t = *(const float2*)(tmp + rowb + n);
                float2 v = *(const float2*)(value + rowb + n);
                v.x += g * (t.x + acc[mt][nt][half * 2 + 0] * invs[n]);
                v.y += g * (t.y + acc[mt][nt][half * 2 + 1] * invs[n + 1]);
                *(float2*)(value + rowb + n) = v;
            }
        }
}

// ---------------- launch ----------------
extern "C" void kernel_launch(void* const* d_in, const int* in_sizes, int n_in,
                              void* d_out, int out_size)
{
    const float* low   = (const float*)d_in[0];
    const float* high  = (const float*)d_in[1];
    const float* Wc1   = (const float*)d_in[2];
    const float* bc1   = (const float*)d_in[3];
    const float* Wc2   = (const float*)d_in[4];
    const float* bc2   = (const float*)d_in[5];
    const float* Wq    = (const float*)d_in[6];
    const float* bq    = (const float*)d_in[7];
    const float* Wk    = (const float*)d_in[8];
    const float* bk    = (const float*)d_in[9];
    const float* Wv    = (const float*)d_in[10];
    const float* bv    = (const float*)d_in[11];
    const float* gamma = (const float*)d_in[12];
    const float* Wb    = (const float*)d_in[13];
    const float* bng   = (const float*)d_in[14];
    const float* bnb   = (const float*)d_in[15];
    const float* bnm   = (const float*)d_in[16];
    const float* bnv   = (const float*)d_in[17];
    float* out = (float*)d_out;

    float *highup, *query, *value, *pv, *tmp, *pq, *pk, *att, *tot;
    cudaGetSymbolAddress((void**)&highup, g_highup);
    cudaGetSymbolAddress((void**)&query,  g_query);
    cudaGetSymbolAddress((void**)&value,  g_value);
    cudaGetSymbolAddress((void**)&pv,     g_pv);
    cudaGetSymbolAddress((void**)&tmp,    g_tmp);
    cudaGetSymbolAddress((void**)&pq,     g_pq);
    cudaGetSymbolAddress((void**)&pk,     g_pk);
    cudaGetSymbolAddress((void**)&att,    g_att);
    cudaGetSymbolAddress((void**)&tot,    g_tot);

    // 1. bilinear 2x upsample
    upsample_kernel<<<65536, 256>>>(high, highup);

    // 2. query = Wc1 @ concat(highup, low) + bc1
    gemm_dual<<<dim3(128, 1, BB), 256>>>(Wc1, 512, bc1, highup, 256, low, 256,
                                         query, 128, nullptr, nullptr, nullptr, nullptr);
    // 3. value = Wc2 @ highup + bc2
    gemm_dual<<<dim3(128, 1, BB), 256>>>(Wc2, 256, bc2, highup, 256, nullptr, 0,
                                         value, 128, nullptr, nullptr, nullptr, nullptr);

    // 4. pq (query fixed across iterations)
    proj16_kernel<<<dim3(16, BB), 256>>>(Wq, bq, query, pq);

    // 5. two criss-cross attention iterations (softmax folded into e-kernels + agg)
    for (int it = 0; it < 2; it++) {
        proj16_kernel<<<dim3(16, BB), 256>>>(Wk, bk, value, pk);
        gemm_dual<<<dim3(128, 1, BB), 256>>>(Wv, 128, bv, value, 128, nullptr, 0,
                                             pv, 128, nullptr, nullptr, nullptr, nullptr);
        eH_kernel<<<dim3(128, BB), 256>>>(pq, pk, att, tot);
        eW_kernel<<<dim3(128, BB), 256>>>(pq, pk, att, tot);
        aggH_mma<<<dim3(128, BB), 256>>>(pv, att, tot, tmp);
        aggW_mma<<<dim3(128, BB), 256>>>(pv, att, tot, tmp, value, gamma);
    }

    // 6. out = ReLU(BN(Wb @ concat(value, highup)))
    gemm_dual<<<dim3(128, 2, BB), 256>>>(Wb, 384, nullptr, value, 128, highup, 256,
                                         out, 256, bng, bnb, bnm, bnv);
}

// round 7
// speedup vs baseline: 1.0284x; 1.0284x over previous
#include <cuda_runtime.h>
#include <math.h>

#define BB   4
#define HWSZ 16384        // 128*128

// ---------------- scratch (device globals: no allocation allowed) ----------------
__device__ float g_highup[16777216];  // (4,256,128,128)
__device__ float g_query [ 8388608];  // (4,128,128,128)
__device__ float g_value [ 8388608];
__device__ float g_pv    [ 8388608];
__device__ float g_tmp   [ 8388608];
__device__ float g_pq    [ 1048576];  // (4,16,128,128)
__device__ float g_pk    [ 1048576];
__device__ float g_att   [16777216];  // (4,128,128,256) exp(logits)
__device__ float g_tot   [   65536];  // (4,128,128) softmax denominators

// ---------------- tf32 helpers ----------------
__device__ __forceinline__ unsigned f2tf(float f) {
    unsigned r;
    asm("cvt.rna.tf32.f32 %0, %1;" : "=r"(r) : "f"(f));
    return r;
}

__device__ __forceinline__ void mma8(float* d, const unsigned* a, const unsigned* b) {
    asm("mma.sync.aligned.m16n8k8.row.col.f32.tf32.tf32.f32 "
        "{%0,%1,%2,%3},{%4,%5,%6,%7},{%8,%9},{%0,%1,%2,%3};"
        : "+f"(d[0]), "+f"(d[1]), "+f"(d[2]), "+f"(d[3])
        : "r"(a[0]), "r"(a[1]), "r"(a[2]), "r"(a[3]), "r"(b[0]), "r"(b[1]));
}

// One K=16 chunk from staged smem tiles. Warp tile 64x32 (4 m x 4 n of 16x8 mmas).
__device__ __forceinline__ void tile_mma(const unsigned (*As)[136],
                                         const unsigned (*Bs)[136],
                                         float acc[4][4][4],
                                         int lane, int mbase, int nbase)
{
#pragma unroll
    for (int kt = 0; kt < 2; kt++) {
        unsigned a[4][4], b[4][2];
        const int kb = kt * 8 + (lane & 3);
        const int rq = lane >> 2;
#pragma unroll
        for (int mt = 0; mt < 4; mt++) {
            int m = mbase + mt * 16 + rq;
            a[mt][0] = As[kb][m];
            a[mt][1] = As[kb][m + 8];
            a[mt][2] = As[kb + 4][m];
            a[mt][3] = As[kb + 4][m + 8];
        }
#pragma unroll
        for (int nt = 0; nt < 4; nt++) {
            int n = nbase + nt * 8 + rq;
            b[nt][0] = Bs[kb][n];
            b[nt][1] = Bs[kb + 4][n];
        }
#pragma unroll
        for (int mt = 0; mt < 4; mt++)
#pragma unroll
            for (int nt = 0; nt < 4; nt++)
                mma8(acc[mt][nt], a[mt], b[nt]);
    }
}

// ---------------- bilinear 2x upsample ----------------
__global__ __launch_bounds__(256) void upsample_kernel(const float* __restrict__ in,
                                                       float* __restrict__ out) {
    int idx = blockIdx.x * 256 + threadIdx.x;
    int ox = idx & 127;
    int oy = (idx >> 7) & 127;
    int bc = idx >> 14;
    float fy = 0.5f * oy - 0.25f;
    float fx = 0.5f * ox - 0.25f;
    int y0 = (int)floorf(fy); float wy = fy - (float)y0;
    int x0 = (int)floorf(fx); float wx = fx - (float)x0;
    int y1 = min(y0 + 1, 63); y0 = max(y0, 0);
    int x1 = min(x0 + 1, 63); x0 = max(x0, 0);
    const float* p = in + (size_t)bc * 4096;
    float v00 = p[y0 * 64 + x0], v01 = p[y0 * 64 + x1];
    float v10 = p[y1 * 64 + x0], v11 = p[y1 * 64 + x1];
    float top = v00 + wx * (v01 - v00);
    float bot = v10 + wx * (v11 - v10);
    out[idx] = top + wy * (bot - top);
}

// ---------------- dual-input tf32 GEMM (single-buffered, R4-proven) ----------------
__global__ __launch_bounds__(256) void gemm_dual(
    const float* __restrict__ Wm, int ldw,
    const float* __restrict__ bias,
    const float* __restrict__ X1, int I1,
    const float* __restrict__ X2, int I2,
    float* __restrict__ Y, int O,
    const float* __restrict__ bng, const float* __restrict__ bnb,
    const float* __restrict__ bnm, const float* __restrict__ bnv)
{
    __shared__ unsigned As[16][136];
    __shared__ unsigned Bs[16][136];
    const int b  = blockIdx.z;
    const int to = blockIdx.y * 128;
    const int tp = blockIdx.x * 128;
    const int tid  = threadIdx.x;
    const int warp = tid >> 5;
    const int lane = tid & 31;
    const int mbase = (warp >> 2) * 64;
    const int nbase = (warp & 3) * 32;

    const int am  = tid >> 1;
    const int akq = (tid & 1) * 8;
    const int bk  = tid >> 4;
    const int bn  = (tid & 15) * 8;

    const float* X1p = X1 + (size_t)b * I1 * HWSZ;
    const float* X2p = X2 ? X2 + (size_t)b * I2 * HWSZ : nullptr;
    const int K = I1 + I2;

    float acc[4][4][4] = {};

    for (int k0 = 0; k0 < K; k0 += 16) {
        const float* Wp = Wm + (size_t)(to + am) * ldw + k0 + akq;
        float4 w0 = *(const float4*)Wp;
        float4 w1 = *(const float4*)(Wp + 4);
        int kr = k0 + bk;
        const float* Xp = (kr < I1) ? (X1p + (size_t)kr * HWSZ)
                                    : (X2p + (size_t)(kr - I1) * HWSZ);
        Xp += tp + bn;
        float4 x0 = *(const float4*)Xp;
        float4 x1 = *(const float4*)(Xp + 4);

        __syncthreads();
        As[akq + 0][am] = f2tf(w0.x);
        As[akq + 1][am] = f2tf(w0.y);
        As[akq + 2][am] = f2tf(w0.z);
        As[akq + 3][am] = f2tf(w0.w);
        As[akq + 4][am] = f2tf(w1.x);
        As[akq + 5][am] = f2tf(w1.y);
        As[akq + 6][am] = f2tf(w1.z);
        As[akq + 7][am] = f2tf(w1.w);
        *(uint4*)&Bs[bk][bn]     = make_uint4(f2tf(x0.x), f2tf(x0.y), f2tf(x0.z), f2tf(x0.w));
        *(uint4*)&Bs[bk][bn + 4] = make_uint4(f2tf(x1.x), f2tf(x1.y), f2tf(x1.z), f2tf(x1.w));
        __syncthreads();

        tile_mma(As, Bs, acc, lane, mbase, nbase);
    }

    const bool dobn = (bng != nullptr);
#pragma unroll
    for (int mt = 0; mt < 4; mt++) {
#pragma unroll
        for (int half = 0; half < 2; half++) {
            int o = to + mbase + mt * 16 + (lane >> 2) + half * 8;
            float bia = bias ? bias[o] : 0.0f;
            float sc = 1.0f, mn = 0.0f, bt = 0.0f;
            if (dobn) {
                sc = bng[o] * rsqrtf(bnv[o] + 1e-5f);
                mn = bnm[o];
                bt = bnb[o];
            }
            size_t rowb = ((size_t)b * O + o) * HWSZ + tp;
#pragma unroll
            for (int nt = 0; nt < 4; nt++) {
                int n = nbase + nt * 8 + 2 * (lane & 3);
                float v0 = acc[mt][nt][half * 2 + 0] + bia;
                float v1 = acc[mt][nt][half * 2 + 1] + bia;
                if (dobn) {
                    v0 = fmaxf((v0 - mn) * sc + bt, 0.0f);
                    v1 = fmaxf((v1 - mn) * sc + bt, 0.0f);
                }
                *(float2*)(Y + rowb + n) = make_float2(v0, v1);
            }
        }
    }
}

// ---------------- small projection O=16, I=128 (R4-proven scalar version) ----------------
__global__ __launch_bounds__(256) void proj16_kernel(
    const float* __restrict__ Wm, const float* __restrict__ bias,
    const float* __restrict__ X, float* __restrict__ Y)
{
    __shared__ float Ws[16 * 128];
    const int b = blockIdx.y;
    const int p = blockIdx.x * 256 + threadIdx.x;
    for (int i = threadIdx.x; i < 2048; i += 256) Ws[i] = Wm[i];
    __syncthreads();
    float acc[16];
#pragma unroll
    for (int o = 0; o < 16; o++) acc[o] = bias[o];
    const float* Xp = X + (size_t)b * 128 * HWSZ + p;
#pragma unroll 4
    for (int i = 0; i < 128; i++) {
        float xv = Xp[(size_t)i * HWSZ];
#pragma unroll
        for (int o = 0; o < 16; o++) acc[o] += Ws[o * 128 + i] * xv;
    }
    float* Yp = Y + (size_t)b * 16 * HWSZ + p;
#pragma unroll
    for (int o = 0; o < 16; o++) Yp[(size_t)o * HWSZ] = acc[o];
}

// ---------------- criss-cross logits -> exp + row-sum (softmax fused out) ----------------
// eH: att[b,h,w,x] = exp(sum_c pq[c,h,w]*pk[c,x,w]), 0 on diag; tot[b,h,w] = sum_x (plain store)
__global__ __launch_bounds__(256) void eH_kernel(const float* __restrict__ pq,
                                                 const float* __restrict__ pk,
                                                 float* __restrict__ att,
                                                 float* __restrict__ tot)
{
    __shared__ float PQ[16][128];
    __shared__ float PK[16][128];
    __shared__ float ws[64][8];
    const int w = blockIdx.x, b = blockIdx.y;
    for (int i = threadIdx.x; i < 2048; i += 256) {
        int c = i >> 7, h = i & 127;
        size_t idx = (((size_t)b * 16 + c) * 128 + h) * 128 + w;
        PQ[c][h] = pq[idx];
        PK[c][h] = pk[idx];
    }
    __syncthreads();
    const int x    = threadIdx.x & 127;
    const int h0   = threadIdx.x >> 7;
    const int warp = threadIdx.x >> 5;
    const int lane = threadIdx.x & 31;
    for (int j = 0; j < 64; j++) {
        int h = 2 * j + h0;
        float s = 0.0f;
#pragma unroll
        for (int c = 0; c < 16; c++) s += PQ[c][h] * PK[c][x];
        float e = (h == x) ? 0.0f : __expf(s);
        att[(((size_t)b * 128 + h) * 128 + w) * 256 + x] = e;
        float p = e;
#pragma unroll
        for (int o = 16; o; o >>= 1) p += __shfl_xor_sync(0xffffffffu, p, o);
        if (lane == 0) ws[j][warp] = p;
    }
    __syncthreads();
    if (threadIdx.x < 128) {
        int h = threadIdx.x;
        int j = h >> 1, g = (h & 1) * 4;
        float s = ws[j][g] + ws[j][g + 1] + ws[j][g + 2] + ws[j][g + 3];
        tot[((size_t)b * 128 + h) * 128 + w] = s;
    }
}

// eW: att[b,h,w,128+x] = exp(sum_c pq[c,h,w]*pk[c,h,x]); tot[b,h,w] += sum_x
__global__ __launch_bounds__(256) void eW_kernel(const float* __restrict__ pq,
                                                 const float* __restrict__ pk,
                                                 float* __restrict__ att,
                                                 float* __restrict__ tot)
{
    __shared__ float PQ[16][128];
    __shared__ float PK[16][128];
    __shared__ float ws[64][8];
    const int h = blockIdx.x, b = blockIdx.y;
    for (int i = threadIdx.x; i < 2048; i += 256) {
        int c = i >> 7, w = i & 127;
        size_t idx = (((size_t)b * 16 + c) * 128 + h) * 128 + w;
        PQ[c][w] = pq[idx];
        PK[c][w] = pk[idx];
    }
    __syncthreads();
    const int x    = threadIdx.x & 127;
    const int w0   = threadIdx.x >> 7;
    const int warp = threadIdx.x >> 5;
    const int lane = threadIdx.x & 31;
    for (int j = 0; j < 64; j++) {
        int w = 2 * j + w0;
        float s = 0.0f;
#pragma unroll
        for (int c = 0; c < 16; c++) s += PQ[c][w] * PK[c][x];
        float e = __expf(s);
        att[(((size_t)b * 128 + h) * 128 + w) * 256 + 128 + x] = e;
        float p = e;
#pragma unroll
        for (int o = 16; o; o >>= 1) p += __shfl_xor_sync(0xffffffffu, p, o);
        if (lane == 0) ws[j][warp] = p;
    }
    __syncthreads();
    if (threadIdx.x < 128) {
        int w = threadIdx.x;
        int j = w >> 1, g = (w & 1) * 4;
        float s = ws[j][g] + ws[j][g + 1] + ws[j][g + 2] + ws[j][g + 3];
        size_t idx = ((size_t)b * 128 + h) * 128 + w;
        tot[idx] += s;        // eH already stored; kernels serialize on stream
    }
}

// ---------------- aggH: tmp[b,c,h,w] = inv[h,w] * sum_x pv[b,c,x,w]*attH (single-buffered) ----
__global__ __launch_bounds__(256) void aggH_mma(const float* __restrict__ pv,
                                                const float* __restrict__ att,
                                                const float* __restrict__ tot,
                                                float* __restrict__ tmp)
{
    __shared__ unsigned As[16][136];
    __shared__ unsigned Bs[16][136];
    __shared__ float invs[128];
    const int w = blockIdx.x, b = blockIdx.y;
    const int tid  = threadIdx.x;
    const int warp = tid >> 5;
    const int lane = tid & 31;
    const int mbase = (warp >> 2) * 64;
    const int nbase = (warp & 3) * 32;

    const int cm = tid >> 1;
    const int xq = (tid & 1) * 8;

    if (tid < 128)
        invs[tid] = 1.0f / tot[((size_t)b * 128 + tid) * 128 + w];

    float acc[4][4][4] = {};
    const float* pvp = pv + (((size_t)b * 128 + cm) * 128) * 128 + w;
    const float* atp = att + (((size_t)b * 128 + cm) * 128 + w) * 256;

    for (int k0 = 0; k0 < 128; k0 += 16) {
        float av[8];
#pragma unroll
        for (int j = 0; j < 8; j++) av[j] = pvp[(size_t)(k0 + xq + j) * 128];
        float4 b0 = *(const float4*)(atp + k0 + xq);
        float4 b1 = *(const float4*)(atp + k0 + xq + 4);

        __syncthreads();
#pragma unroll
        for (int j = 0; j < 8; j++) As[xq + j][cm] = f2tf(av[j]);
        Bs[xq + 0][cm] = f2tf(b0.x);
        Bs[xq + 1][cm] = f2tf(b0.y);
        Bs[xq + 2][cm] = f2tf(b0.z);
        Bs[xq + 3][cm] = f2tf(b0.w);
        Bs[xq + 4][cm] = f2tf(b1.x);
        Bs[xq + 5][cm] = f2tf(b1.y);
        Bs[xq + 6][cm] = f2tf(b1.z);
        Bs[xq + 7][cm] = f2tf(b1.w);
        __syncthreads();

        tile_mma(As, Bs, acc, lane, mbase, nbase);
    }

#pragma unroll
    for (int mt = 0; mt < 4; mt++)
#pragma unroll
        for (int half = 0; half < 2; half++) {
            int c = mbase + mt * 16 + (lane >> 2) + half * 8;
            size_t cb = (((size_t)b * 128 + c) * 128) * 128 + w;
#pragma unroll
            for (int nt = 0; nt < 4; nt++) {
                int h = nbase + nt * 8 + 2 * (lane & 3);
                tmp[cb + (size_t)h * 128]       = acc[mt][nt][half * 2 + 0] * invs[h];
                tmp[cb + (size_t)(h + 1) * 128] = acc[mt][nt][half * 2 + 1] * invs[h + 1];
            }
        }
}

// ---------------- aggW + update: value += gamma*(tmp + inv[h,w]*sum_x pv*attW) -----------
__global__ __launch_bounds__(256) void aggW_mma(const float* __restrict__ pv,
                                                const float* __restrict__ att,
                                                const float* __restrict__ tot,
                                                const float* __restrict__ tmp,
                                                float* __restrict__ value,
                                                const float* __restrict__ gamma_p)
{
    __shared__ unsigned As[16][136];
    __shared__ unsigned Bs[16][136];
    __shared__ float invs[128];
    const int h = blockIdx.x, b = blockIdx.y;
    const int tid  = threadIdx.x;
    const int warp = tid >> 5;
    const int lane = tid & 31;
    const int mbase = (warp >> 2) * 64;
    const int nbase = (warp & 3) * 32;

    const int cm = tid >> 1;
    const int xq = (tid & 1) * 8;

    if (tid < 128)
        invs[tid] = 1.0f / tot[((size_t)b * 128 + h) * 128 + tid];

    float acc[4][4][4] = {};
    const float* pvp = pv + (((size_t)b * 128 + cm) * 128 + h) * 128;
    const float* atp = att + (((size_t)b * 128 + h) * 128 + cm) * 256 + 128;

    for (int k0 = 0; k0 < 128; k0 += 16) {
        float4 a0 = *(const float4*)(pvp + k0 + xq);
        float4 a1 = *(const float4*)(pvp + k0 + xq + 4);
        float4 b0 = *(const float4*)(atp + k0 + xq);
        float4 b1 = *(const float4*)(atp + k0 + xq + 4);

        __syncthreads();
        As[xq + 0][cm] = f2tf(a0.x);
        As[xq + 1][cm] = f2tf(a0.y);
        As[xq + 2][cm] = f2tf(a0.z);
        As[xq + 3][cm] = f2tf(a0.w);
        As[xq + 4][cm] = f2tf(a1.x);
        As[xq + 5][cm] = f2tf(a1.y);
        As[xq + 6][cm] = f2tf(a1.z);
        As[xq + 7][cm] = f2tf(a1.w);
        Bs[xq + 0][cm] = f2tf(b0.x);
        Bs[xq + 1][cm] = f2tf(b0.y);
        Bs[xq + 2][cm] = f2tf(b0.z);
        Bs[xq + 3][cm] = f2tf(b0.w);
        Bs[xq + 4][cm] = f2tf(b1.x);
        Bs[xq + 5][cm] = f2tf(b1.y);
        Bs[xq + 6][cm] = f2tf(b1.z);
        Bs[xq + 7][cm] = f2tf(b1.w);
        __syncthreads();

        tile_mma(As, Bs, acc, lane, mbase, nbase);
    }

    const float g = *gamma_p;
#pragma unroll
    for (int mt = 0; mt < 4; mt++)
#pragma unroll
        for (int half = 0; half < 2; half++) {
            int c = mbase + mt * 16 + (lane >> 2) + half * 8;
            size_t rowb = (((size_t)b * 128 + c) * 128 + h) * 128;
#pragma unroll
            for (int nt = 0; nt < 4; nt++) {
                int n = nbase + nt * 8 + 2 * (lane & 3);
                float2 t = *(const float2*)(tmp + rowb + n);
                float2 v = *(const float2*)(value + rowb + n);
                v.x += g * (t.x + acc[mt][nt][half * 2 + 0] * invs[n]);
                v.y += g * (t.y + acc[mt][nt][half * 2 + 1] * invs[n + 1]);
                *(float2*)(value + rowb + n) = v;
            }
        }
}

// ---------------- launch ----------------
extern "C" void kernel_launch(void* const* d_in, const int* in_sizes, int n_in,
                              void* d_out, int out_size)
{
    const float* low   = (const float*)d_in[0];
    const float* high  = (const float*)d_in[1];
    const float* Wc1   = (const float*)d_in[2];
    const float* bc1   = (const float*)d_in[3];
    const float* Wc2   = (const float*)d_in[4];
    const float* bc2   = (const float*)d_in[5];
    const float* Wq    = (const float*)d_in[6];
    const float* bq    = (const float*)d_in[7];
    const float* Wk    = (const float*)d_in[8];
    const float* bk    = (const float*)d_in[9];
    const float* Wv    = (const float*)d_in[10];
    const float* bv    = (const float*)d_in[11];
    const float* gamma = (const float*)d_in[12];
    const float* Wb    = (const float*)d_in[13];
    const float* bng   = (const float*)d_in[14];
    const float* bnb   = (const float*)d_in[15];
    const float* bnm   = (const float*)d_in[16];
    const float* bnv   = (const float*)d_in[17];
    float* out = (float*)d_out;

    float *highup, *query, *value, *pv, *tmp, *pq, *pk, *att, *tot;
    cudaGetSymbolAddress((void**)&highup, g_highup);
    cudaGetSymbolAddress((void**)&query,  g_query);
    cudaGetSymbolAddress((void**)&value,  g_value);
    cudaGetSymbolAddress((void**)&pv,     g_pv);
    cudaGetSymbolAddress((void**)&tmp,    g_tmp);
    cudaGetSymbolAddress((void**)&pq,     g_pq);
    cudaGetSymbolAddress((void**)&pk,     g_pk);
    cudaGetSymbolAddress((void**)&att,    g_att);
    cudaGetSymbolAddress((void**)&tot,    g_tot);

    // 1. bilinear 2x upsample
    upsample_kernel<<<65536, 256>>>(high, highup);

    // 2. query = Wc1 @ concat(highup, low) + bc1
    gemm_dual<<<dim3(128, 1, BB), 256>>>(Wc1, 512, bc1, highup, 256, low, 256,
                                         query, 128, nullptr, nullptr, nullptr, nullptr);
    // 3. value = Wc2 @ highup + bc2
    gemm_dual<<<dim3(128, 1, BB), 256>>>(Wc2, 256, bc2, highup, 256, nullptr, 0,
                                         value, 128, nullptr, nullptr, nullptr, nullptr);

    // 4. pq (query fixed across iterations)
    proj16_kernel<<<dim3(64, BB), 256>>>(Wq, bq, query, pq);

    // 5. two criss-cross attention iterations (softmax folded into e-kernels + agg)
    for (int it = 0; it < 2; it++) {
        proj16_kernel<<<dim3(64, BB), 256>>>(Wk, bk, value, pk);
        gemm_dual<<<dim3(128, 1, BB), 256>>>(Wv, 128, bv, value, 128, nullptr, 0,
                                             pv, 128, nullptr, nullptr, nullptr, nullptr);
        eH_kernel<<<dim3(128, BB), 256>>>(pq, pk, att, tot);
        eW_kernel<<<dim3(128, BB), 256>>>(pq, pk, att, tot);
        aggH_mma<<<dim3(128, BB), 256>>>(pv, att, tot, tmp);
        aggW_mma<<<dim3(128, BB), 256>>>(pv, att, tot, tmp, value, gamma);
    }

    // 6. out = ReLU(BN(Wb @ concat(value, highup)))
    gemm_dual<<<dim3(128, 2, BB), 256>>>(Wb, 384, nullptr, value, 128, highup, 256,
                                         out, 256, bng, bnb, bnm, bnv);
}